// round 3
// baseline (speedup 1.0000x reference)
#include <cuda_runtime.h>
#include <math.h>

#define NEV   128
#define NSAMP 131072
#define NFFT  262144
#define NFR   128
#define WINL  1024
#define CPD   16
#define NCP   512
#define NVO   8
#define NVB   16
#define HID   128
#define KSP   128
#define LSTR  576

__device__ float2 g_tw[NFFT];
__device__ float2 g_spec[(size_t)NEV * NFFT];
__device__ float2 g_vspec[(size_t)NVB * NFFT];
__device__ float  g_sig[(size_t)NEV * NSAMP];
__device__ float  g_hs[(size_t)NEV * NFR * HID];
__device__ float  g_ctrl[NEV * NFR * CPD];
__device__ float  g_M[NVO * HID * CPD];
__device__ int    g_vidx[NEV], g_ridx[NEV], g_shift[NEV];
__device__ float  g_m0[NEV], g_m1[NEV], g_amp[NEV];

__device__ __forceinline__ int skew(int i){ return i + (i >> 3); }
__device__ __forceinline__ float2 cadd(float2 a, float2 b){ return make_float2(a.x+b.x, a.y+b.y); }
__device__ __forceinline__ float2 csub(float2 a, float2 b){ return make_float2(a.x-b.x, a.y-b.y); }
__device__ __forceinline__ float2 cmul(float2 a, float2 b){ return make_float2(a.x*b.x - a.y*b.y, a.x*b.y + a.y*b.x); }
__device__ __forceinline__ float2 cmulc(float2 a, float2 b){ return make_float2(a.x*b.x + a.y*b.y, a.y*b.x - a.x*b.y); }
__device__ __forceinline__ int rev9(int p){ return ((p & 7) << 6) | (p & 56) | (p >> 6); }

template<bool INV>
__device__ __forceinline__ float2 mulmi(float2 a){
    return INV ? make_float2(-a.y, a.x) : make_float2(a.y, -a.x);
}

template<bool INV>
__device__ __forceinline__ void dft8(float2* v){
    float2 t0 = cadd(v[0], v[4]), t1 = csub(v[0], v[4]);
    float2 t2 = cadd(v[2], v[6]), t3 = mulmi<INV>(csub(v[2], v[6]));
    float2 t4 = cadd(v[1], v[5]), t5 = csub(v[1], v[5]);
    float2 t6 = cadd(v[3], v[7]), t7 = mulmi<INV>(csub(v[3], v[7]));
    float2 a0 = cadd(t0, t2), a2 = csub(t0, t2);
    float2 a1 = cadd(t1, t3), a3 = csub(t1, t3);
    float2 b0 = cadd(t4, t6), b2 = csub(t4, t6);
    float2 b1 = cadd(t5, t7), b3 = csub(t5, t7);
    const float r = 0.70710678118654752440f;
    float2 w1 = INV ? make_float2(r,  r) : make_float2(r, -r);
    float2 w3 = INV ? make_float2(-r, r) : make_float2(-r, -r);
    b1 = cmul(b1, w1); b2 = mulmi<INV>(b2); b3 = cmul(b3, w3);
    v[0] = cadd(a0, b0); v[4] = csub(a0, b0);
    v[1] = cadd(a1, b1); v[5] = csub(a1, b1);
    v[2] = cadd(a2, b2); v[6] = csub(a2, b2);
    v[3] = cadd(a3, b3); v[7] = csub(a3, b3);
}

// DIF 512 = radix-8^3, natural in -> octal-digit-reversed out.
__device__ __forceinline__ void dif512(float2* L, int t){
    float2 v[8];
    #pragma unroll
    for(int m = 0; m < 8; m++) v[m] = L[skew(t + 64*m)];
    dft8<false>(v);
    #pragma unroll
    for(int m = 1; m < 8; m++) v[m] = cmul(v[m], g_tw[(t*m) << 9]);
    #pragma unroll
    for(int m = 0; m < 8; m++) L[skew(t + 64*m)] = v[m];
    __syncthreads();
    int base = (t >> 3) << 6, j = t & 7;
    #pragma unroll
    for(int m = 0; m < 8; m++) v[m] = L[skew(base + j + 8*m)];
    dft8<false>(v);
    #pragma unroll
    for(int m = 1; m < 8; m++) v[m] = cmul(v[m], g_tw[(j*m) << 12]);
    #pragma unroll
    for(int m = 0; m < 8; m++) L[skew(base + j + 8*m)] = v[m];
    __syncthreads();
    base = t << 3;
    #pragma unroll
    for(int m = 0; m < 8; m++) v[m] = L[skew(base + m)];
    dft8<false>(v);
    #pragma unroll
    for(int m = 0; m < 8; m++) L[skew(base + m)] = v[m];
}

// DIT 512: digit-reversed in -> natural out, conjugate twiddles (unscaled inverse).
__device__ __forceinline__ void dit512(float2* L, int t){
    float2 v[8];
    int base = t << 3;
    #pragma unroll
    for(int m = 0; m < 8; m++) v[m] = L[skew(base + m)];
    dft8<true>(v);
    #pragma unroll
    for(int m = 0; m < 8; m++) L[skew(base + m)] = v[m];
    __syncthreads();
    base = (t >> 3) << 6; int j = t & 7;
    #pragma unroll
    for(int m = 0; m < 8; m++) v[m] = L[skew(base + j + 8*m)];
    #pragma unroll
    for(int m = 1; m < 8; m++) v[m] = cmulc(v[m], g_tw[(j*m) << 12]);
    dft8<true>(v);
    #pragma unroll
    for(int m = 0; m < 8; m++) L[skew(base + j + 8*m)] = v[m];
    __syncthreads();
    #pragma unroll
    for(int m = 0; m < 8; m++) v[m] = L[skew(t + 64*m)];
    #pragma unroll
    for(int m = 1; m < 8; m++) v[m] = cmulc(v[m], g_tw[(t*m) << 9]);
    dft8<true>(v);
    #pragma unroll
    for(int m = 0; m < 8; m++) L[skew(t + 64*m)] = v[m];
}

__global__ void k_twiddle(){
    int k = blockIdx.x * blockDim.x + threadIdx.x;
    if(k < NFFT){
        double a = -6.283185307179586476925286766559 * (double)k / (double)NFFT;
        double s, c; sincos(a, &s, &c);
        g_tw[k] = make_float2((float)c, (float)s);
    }
}

__global__ void k_zero(float* out, int nel){
    int i = blockIdx.x * blockDim.x + threadIdx.x;
    if(i < nel) out[i] = 0.f;
}

__global__ __launch_bounds__(256) void k_prep(
    const float* __restrict__ voice, const float* __restrict__ cpc,
    const float* __restrict__ amp,   const float* __restrict__ room,
    const float* __restrict__ mix,   const float* __restrict__ times,
    const float* __restrict__ cp_table)
{
    int n = blockIdx.x, tid = threadIdx.x;
    __shared__ float sv[256];
    __shared__ int   si[256];
    __shared__ int   s_cidx, s_cnt;

    // argmax over 512 control planes (first index on ties)
    float best = -1e30f; int bi = 0;
    for(int j = tid; j < NCP; j += 256){
        float v = cpc[n*NCP + j];
        if(v > best){ best = v; bi = j; }
    }
    sv[tid] = best; si[tid] = bi; __syncthreads();
    for(int s = 128; s > 0; s >>= 1){
        if(tid < s){
            if(sv[tid+s] > sv[tid] || (sv[tid+s] == sv[tid] && si[tid+s] < si[tid])){
                sv[tid] = sv[tid+s]; si[tid] = si[tid+s];
            }
        }
        __syncthreads();
    }
    if(tid == 0){
        s_cidx = si[0];
        float b = -1e30f; int ii = 0;
        for(int j = 0; j < NFR; j++){ float v = times[n*NFR + j]; if(v > b){ b = v; ii = j; } }
        g_shift[n] = ii * (NSAMP / NFR);
        b = -1e30f; ii = 0;
        for(int j = 0; j < NVO; j++){ float v = voice[n*NVO + j]; if(v > b){ b = v; ii = j; } }
        g_vidx[n] = ii;
        b = -1e30f; ii = 0;
        for(int j = 0; j < NVB; j++){ float v = room[n*NVB + j]; if(v > b){ b = v; ii = j; } }
        g_ridx[n] = ii;
        float x0 = mix[n*2], x1 = mix[n*2 + 1];
        float mm = fmaxf(x0, x1);
        float e0 = expf(x0 - mm), e1 = expf(x1 - mm);
        g_m0[n] = e0 / (e0 + e1);
        g_m1[n] = e1 / (e0 + e1);
        g_amp[n] = fabsf(amp[n]);
    }
    __syncthreads();

    // top-K threshold over selected cp row (values in [0,1) -> bit-monotone)
    const float* row = cp_table + (size_t)s_cidx * (NFR*CPD);
    float rv[8];
    #pragma unroll
    for(int j = 0; j < 8; j++) rv[j] = row[tid + 256*j];
    unsigned lo = 0u, hi = 0x7F800000u;
    while(hi - lo > 1u){
        unsigned mid = lo + ((hi - lo) >> 1);
        int c = 0;
        #pragma unroll
        for(int j = 0; j < 8; j++) c += (__float_as_uint(rv[j]) >= mid) ? 1 : 0;
        si[tid] = c; __syncthreads();
        for(int s = 128; s > 0; s >>= 1){
            if(tid < s) si[tid] += si[tid+s];
            __syncthreads();
        }
        if(tid == 0) s_cnt = si[0];
        __syncthreads();
        if(s_cnt >= KSP) lo = mid; else hi = mid;
    }
    // ctrl[f][c] = relu(row[c*NFR+f] if top-K else 0)
    for(int idx = tid; idx < NFR*CPD; idx += 256){
        int f = idx >> 4, c = idx & 15;
        float v = row[c*NFR + f];
        float keep = (__float_as_uint(v) >= lo) ? v : 0.f;
        g_ctrl[n*NFR*CPD + idx] = fmaxf(keep, 0.f);
    }
}

// M[v] = W_ih[v] @ W_in[v], fp64 accumulation
__global__ __launch_bounds__(256) void k_collapse(
    const float* __restrict__ w_ih, const float* __restrict__ w_in)
{
    int v = blockIdx.x, tid = threadIdx.x;
    for(int o = tid; o < HID*CPD; o += 256){
        int i = o >> 4, c = o & 15;
        const float* wr = w_ih + ((size_t)v*HID + i) * WINL;
        const float* wc = w_in + (size_t)v*WINL*CPD + c;
        double acc = 0.0;
        for(int w = 0; w < WINL; w++)
            acc += (double)wr[w] * (double)wc[(size_t)w*CPD];
        g_M[(v*HID + i)*CPD + c] = (float)acc;
    }
}

// persistent RNN: one block/event
__global__ __launch_bounds__(256) void k_rnn(const float* __restrict__ w_hh){
    int n = blockIdx.x, t = threadIdx.x;
    int i = t & 127, half = t >> 7;
    int v = g_vidx[n];
    __shared__ float ctrl_s[NFR*CPD];
    __shared__ float h_s[HID];
    __shared__ float part_s[256];

    float W[64];
    const float* wh = w_hh + ((size_t)v*HID + i) * HID + half*64;
    #pragma unroll
    for(int k = 0; k < 64; k++) W[k] = wh[k];
    float M[CPD];
    const float* mp = g_M + (v*HID + i)*CPD;
    #pragma unroll
    for(int c = 0; c < CPD; c++) M[c] = mp[c];
    for(int idx = t; idx < NFR*CPD; idx += 256) ctrl_s[idx] = g_ctrl[n*NFR*CPD + idx];
    if(t < HID) h_s[t] = 0.f;
    __syncthreads();

    float* hsout = g_hs + (size_t)n*NFR*HID;
    for(int f = 0; f < NFR; f++){
        float p = 0.f;
        const float* hb = h_s + half*64;
        #pragma unroll
        for(int k = 0; k < 64; k++) p += W[k] * hb[k];
        part_s[t] = p;
        __syncthreads();
        if(half == 0){
            float inp = 0.f;
            #pragma unroll
            for(int c = 0; c < CPD; c++) inp += M[c] * ctrl_s[f*CPD + c];
            float h = tanhf(p + part_s[t + 128] + inp);
            h_s[i] = h;
            hsout[f*HID + i] = h;
        }
        __syncthreads();
    }
}

// sig[f,w] = sin( hs[f,:] . w_out[v,w,:] )
__global__ __launch_bounds__(256) void k_wout(const float* __restrict__ w_out){
    int wt = blockIdx.x, n = blockIdx.y, t = threadIdx.x;
    int v = g_vidx[n];
    const float* A  = g_hs + (size_t)n*NFR*HID;
    const float* Bm = w_out + (size_t)v*WINL*HID + (size_t)wt*128*HID;
    __shared__ float As[32*132];
    __shared__ float Bs[32*132];
    int tx = t & 15, ty = t >> 4;
    int f0 = ty*8, w0 = tx*8;
    float acc[8][8];
    #pragma unroll
    for(int i = 0; i < 8; i++)
        #pragma unroll
        for(int j = 0; j < 8; j++) acc[i][j] = 0.f;

    for(int ks = 0; ks < 4; ks++){
        int k0 = ks*32;
        #pragma unroll
        for(int r = 0; r < 4; r++){
            int idx4 = t + 256*r;
            int rr = idx4 >> 3, kk4 = idx4 & 7;
            float4 va = *(const float4*)(A  + (size_t)rr*HID + k0 + kk4*4);
            float4 vb = *(const float4*)(Bm + (size_t)rr*HID + k0 + kk4*4);
            As[(kk4*4+0)*132 + rr] = va.x; As[(kk4*4+1)*132 + rr] = va.y;
            As[(kk4*4+2)*132 + rr] = va.z; As[(kk4*4+3)*132 + rr] = va.w;
            Bs[(kk4*4+0)*132 + rr] = vb.x; Bs[(kk4*4+1)*132 + rr] = vb.y;
            Bs[(kk4*4+2)*132 + rr] = vb.z; Bs[(kk4*4+3)*132 + rr] = vb.w;
        }
        __syncthreads();
        #pragma unroll
        for(int k = 0; k < 32; k++){
            float4 a0 = *(const float4*)&As[k*132 + f0];
            float4 a1 = *(const float4*)&As[k*132 + f0 + 4];
            float4 b0 = *(const float4*)&Bs[k*132 + w0];
            float4 b1 = *(const float4*)&Bs[k*132 + w0 + 4];
            float a[8] = {a0.x,a0.y,a0.z,a0.w,a1.x,a1.y,a1.z,a1.w};
            float b[8] = {b0.x,b0.y,b0.z,b0.w,b1.x,b1.y,b1.z,b1.w};
            #pragma unroll
            for(int i = 0; i < 8; i++)
                #pragma unroll
                for(int j = 0; j < 8; j++) acc[i][j] += a[i]*b[j];
        }
        __syncthreads();
    }
    float* out = g_sig + (size_t)n*NSAMP + wt*128;
    #pragma unroll
    for(int i = 0; i < 8; i++)
        #pragma unroll
        for(int j = 0; j < 8; j++)
            out[(size_t)(f0+i)*WINL + w0 + j] = sinf(acc[i][j]);
}

// F1 column pass (forward) over real input, + inter-pass twiddle.
// SEL=0: verbs -> g_vspec ; SEL=1: g_sig -> g_spec
template<int SEL>
__global__ __launch_bounds__(512) void k_col_fwd(const float* __restrict__ rin_ext){
    __shared__ float2 s[8*LSTR];
    int n = blockIdx.y, col0 = blockIdx.x*8, tid = threadIdx.x;
    const float* src = (SEL == 0 ? rin_ext : g_sig) + (size_t)n*NSAMP;
    for(int idx = tid; idx < 4096; idx += 512){
        int r = idx >> 3, c = idx & 7;
        float val = (r < 256) ? src[(size_t)r*512 + col0 + c] : 0.f;
        s[c*LSTR + skew(r)] = make_float2(val, 0.f);
    }
    __syncthreads();
    dif512(&s[(tid >> 6)*LSTR], tid & 63);
    __syncthreads();
    float2* dst = (SEL == 0 ? g_vspec : g_spec) + (size_t)n*NFFT;
    for(int idx = tid; idx < 4096; idx += 512){
        int r = idx >> 3, c = idx & 7;
        int n2 = col0 + c;
        dst[(size_t)r*512 + n2] = cmul(s[c*LSTR + skew(r)], g_tw[rev9(r)*n2]);
    }
}

// Row pass. MODE 0: F2 on verb spectra. MODE 1: fused F2 + spectral-mul*(1/N) + I1 + conj twiddle.
template<int MODE>
__global__ __launch_bounds__(512) void k_row(){
    __shared__ float2 s[8*LSTR];
    int n = blockIdx.y, row0 = blockIdx.x*8, tid = threadIdx.x;
    float2* base = (MODE == 0 ? g_vspec : g_spec) + (size_t)n*NFFT + (size_t)row0*512;
    for(int idx = tid; idx < 4096; idx += 512){
        int r = idx >> 9, e = idx & 511;
        s[r*LSTR + skew(e)] = base[(size_t)r*512 + e];
    }
    __syncthreads();
    dif512(&s[(tid >> 6)*LSTR], tid & 63);
    __syncthreads();
    if(MODE == 0){
        for(int idx = tid; idx < 4096; idx += 512){
            int r = idx >> 9, e = idx & 511;
            base[(size_t)r*512 + e] = s[r*LSTR + skew(e)];
        }
    } else {
        const float2* vs = g_vspec + (size_t)g_ridx[n]*NFFT + (size_t)row0*512;
        const float sc = 1.f / (float)NFFT;
        for(int idx = tid; idx < 4096; idx += 512){
            int r = idx >> 9, e = idx & 511;
            float2 p = cmul(s[r*LSTR + skew(e)], vs[(size_t)r*512 + e]);
            s[r*LSTR + skew(e)] = make_float2(p.x*sc, p.y*sc);
        }
        __syncthreads();
        dit512(&s[(tid >> 6)*LSTR], tid & 63);
        __syncthreads();
        for(int idx = tid; idx < 4096; idx += 512){
            int r = idx >> 9, e = idx & 511;      // e = natural column after DIT
            int k1 = rev9(row0 + r);
            base[(size_t)r*512 + e] = cmulc(s[r*LSTR + skew(e)], g_tw[k1*e]);
        }
    }
}

// I2 column pass (inverse) + epilogue: wet/dry mix, |amp|, dirac shift-scatter.
__global__ __launch_bounds__(512) void k_col_inv(float* __restrict__ out){
    __shared__ float2 s[8*LSTR];
    int n = blockIdx.y, col0 = blockIdx.x*8, tid = threadIdx.x;
    const float2* src = g_spec + (size_t)n*NFFT;
    for(int idx = tid; idx < 4096; idx += 512){
        int r = idx >> 3, c = idx & 7;
        s[c*LSTR + skew(r)] = src[(size_t)r*512 + col0 + c];
    }
    __syncthreads();
    dit512(&s[(tid >> 6)*LSTR], tid & 63);
    __syncthreads();
    float m0 = g_m0[n], m1 = g_m1[n], am = g_amp[n];
    int d = g_shift[n];
    const float* dry = g_sig + (size_t)n*NSAMP;
    float* o = out + (size_t)n*NSAMP;
    for(int idx = tid; idx < 2048; idx += 512){   // r < 256 only (samples < NSAMP)
        int r = idx >> 3, c = idx & 7;
        int t = r*512 + col0 + c;
        float wet = s[c*LSTR + skew(r)].x;
        float v = (wet * m0 + dry[t] * m1) * am;
        int sdst = t + d;
        if(sdst < NSAMP) o[sdst] = v;
    }
}

extern "C" void kernel_launch(void* const* d_in, const int* in_sizes, int n_in,
                              void* d_out, int out_size) {
    const float* voice = (const float*)d_in[0];
    const float* cpc   = (const float*)d_in[1];
    const float* amp   = (const float*)d_in[2];
    const float* room  = (const float*)d_in[3];
    const float* mix   = (const float*)d_in[4];
    const float* times = (const float*)d_in[5];
    const float* cp_table = (const float*)d_in[6];
    const float* verbs = (const float*)d_in[7];
    const float* w_in  = (const float*)d_in[8];
    const float* w_ih  = (const float*)d_in[9];
    const float* w_hh  = (const float*)d_in[10];
    const float* w_out = (const float*)d_in[11];
    float* out = (float*)d_out;

    k_twiddle<<<512, 512>>>();
    k_zero<<<(out_size + 511)/512, 512>>>(out, out_size);
    k_prep<<<NEV, 256>>>(voice, cpc, amp, room, mix, times, cp_table);
    k_collapse<<<NVO, 256>>>(w_ih, w_in);
    k_rnn<<<NEV, 256>>>(w_hh);
    k_wout<<<dim3(8, NEV), 256>>>(w_out);
    k_col_fwd<0><<<dim3(64, NVB), 512>>>(verbs);
    k_row<0><<<dim3(64, NVB), 512>>>();
    k_col_fwd<1><<<dim3(64, NEV), 512>>>(nullptr);
    k_row<1><<<dim3(64, NEV), 512>>>();
    k_col_inv<<<dim3(64, NEV), 512>>>(out);
}

// round 4
// speedup vs baseline: 1.2228x; 1.2228x over previous
#include <cuda_runtime.h>
#include <math.h>

#define NEV   128
#define NSAMP 131072
#define NFFT  262144
#define NFR   128
#define WINL  1024
#define CPD   16
#define NCP   512
#define NVO   8
#define NVB   16
#define HID   128
#define KSP   128
#define LSTR  576

__device__ float2 g_tw[NFFT];
__device__ float2 g_twtab[1024];
__device__ float2 g_spec[(size_t)NEV * NFFT];
__device__ float2 g_vspec[(size_t)NVB * NFFT];
__device__ float  g_sig[(size_t)NEV * NSAMP];
__device__ float  g_hs[(size_t)NEV * NFR * HID];
__device__ float  g_ctrl[NEV * NFR * CPD];
__device__ float  g_M[NVO * HID * CPD];
__device__ int    g_vidx[NEV], g_ridx[NEV], g_shift[NEV];
__device__ float  g_m0[NEV], g_m1[NEV], g_amp[NEV];

__device__ __forceinline__ int skew(int i){ return i + (i >> 3); }
__device__ __forceinline__ float2 cadd(float2 a, float2 b){ return make_float2(a.x+b.x, a.y+b.y); }
__device__ __forceinline__ float2 csub(float2 a, float2 b){ return make_float2(a.x-b.x, a.y-b.y); }
__device__ __forceinline__ float2 cmul(float2 a, float2 b){ return make_float2(a.x*b.x - a.y*b.y, a.x*b.y + a.y*b.x); }
__device__ __forceinline__ float2 cmulc(float2 a, float2 b){ return make_float2(a.x*b.x + a.y*b.y, a.y*b.x - a.x*b.y); }
__device__ __forceinline__ int rev9(int p){ return ((p & 7) << 6) | (p & 56) | (p >> 6); }

template<bool INV>
__device__ __forceinline__ float2 mulmi(float2 a){
    return INV ? make_float2(-a.y, a.x) : make_float2(a.y, -a.x);
}

template<bool INV>
__device__ __forceinline__ void dft8(float2* v){
    float2 t0 = cadd(v[0], v[4]), t1 = csub(v[0], v[4]);
    float2 t2 = cadd(v[2], v[6]), t3 = mulmi<INV>(csub(v[2], v[6]));
    float2 t4 = cadd(v[1], v[5]), t5 = csub(v[1], v[5]);
    float2 t6 = cadd(v[3], v[7]), t7 = mulmi<INV>(csub(v[3], v[7]));
    float2 a0 = cadd(t0, t2), a2 = csub(t0, t2);
    float2 a1 = cadd(t1, t3), a3 = csub(t1, t3);
    float2 b0 = cadd(t4, t6), b2 = csub(t4, t6);
    float2 b1 = cadd(t5, t7), b3 = csub(t5, t7);
    const float r = 0.70710678118654752440f;
    float2 w1 = INV ? make_float2(r,  r) : make_float2(r, -r);
    float2 w3 = INV ? make_float2(-r, r) : make_float2(-r, -r);
    b1 = cmul(b1, w1); b2 = mulmi<INV>(b2); b3 = cmul(b3, w3);
    v[0] = cadd(a0, b0); v[4] = csub(a0, b0);
    v[1] = cadd(a1, b1); v[5] = csub(a1, b1);
    v[2] = cadd(a2, b2); v[6] = csub(a2, b2);
    v[3] = cadd(a3, b3); v[7] = csub(a3, b3);
}

// DIF 512 = radix-8^3, natural in -> octal-digit-reversed out.
__device__ __forceinline__ void dif512(float2* L, int t){
    float2 v[8];
    #pragma unroll
    for(int m = 0; m < 8; m++) v[m] = L[skew(t + 64*m)];
    dft8<false>(v);
    #pragma unroll
    for(int m = 1; m < 8; m++) v[m] = cmul(v[m], g_tw[(t*m) << 9]);
    #pragma unroll
    for(int m = 0; m < 8; m++) L[skew(t + 64*m)] = v[m];
    __syncthreads();
    int base = (t >> 3) << 6, j = t & 7;
    #pragma unroll
    for(int m = 0; m < 8; m++) v[m] = L[skew(base + j + 8*m)];
    dft8<false>(v);
    #pragma unroll
    for(int m = 1; m < 8; m++) v[m] = cmul(v[m], g_tw[(j*m) << 12]);
    #pragma unroll
    for(int m = 0; m < 8; m++) L[skew(base + j + 8*m)] = v[m];
    __syncthreads();
    base = t << 3;
    #pragma unroll
    for(int m = 0; m < 8; m++) v[m] = L[skew(base + m)];
    dft8<false>(v);
    #pragma unroll
    for(int m = 0; m < 8; m++) L[skew(base + m)] = v[m];
}

// DIT 512: digit-reversed in -> natural out, conjugate twiddles (unscaled inverse).
__device__ __forceinline__ void dit512(float2* L, int t){
    float2 v[8];
    int base = t << 3;
    #pragma unroll
    for(int m = 0; m < 8; m++) v[m] = L[skew(base + m)];
    dft8<true>(v);
    #pragma unroll
    for(int m = 0; m < 8; m++) L[skew(base + m)] = v[m];
    __syncthreads();
    base = (t >> 3) << 6; int j = t & 7;
    #pragma unroll
    for(int m = 0; m < 8; m++) v[m] = L[skew(base + j + 8*m)];
    #pragma unroll
    for(int m = 1; m < 8; m++) v[m] = cmulc(v[m], g_tw[(j*m) << 12]);
    dft8<true>(v);
    #pragma unroll
    for(int m = 0; m < 8; m++) L[skew(base + j + 8*m)] = v[m];
    __syncthreads();
    #pragma unroll
    for(int m = 0; m < 8; m++) v[m] = L[skew(t + 64*m)];
    #pragma unroll
    for(int m = 1; m < 8; m++) v[m] = cmulc(v[m], g_tw[(t*m) << 9]);
    dft8<true>(v);
    #pragma unroll
    for(int m = 0; m < 8; m++) L[skew(t + 64*m)] = v[m];
}

// two 512-entry fp64-accurate tables: A[a]=exp(-2pi i a/512), B[b]=exp(-2pi i b/N)
__global__ void k_twtab(){
    int k = blockIdx.x * blockDim.x + threadIdx.x;
    if(k < 1024){
        double a;
        if(k < 512) a = -6.283185307179586476925286766559 * (double)k / 512.0;
        else        a = -6.283185307179586476925286766559 * (double)(k - 512) / (double)NFFT;
        double s, c; sincos(a, &s, &c);
        g_twtab[k] = make_float2((float)c, (float)s);
    }
}

__global__ void k_twiddle(){
    int k = blockIdx.x * blockDim.x + threadIdx.x;
    if(k < NFFT){
        float2 A = g_twtab[k >> 9];
        float2 B = g_twtab[512 + (k & 511)];
        g_tw[k] = cmul(A, B);
    }
}

__global__ __launch_bounds__(256) void k_prep(
    const float* __restrict__ voice, const float* __restrict__ cpc,
    const float* __restrict__ amp,   const float* __restrict__ room,
    const float* __restrict__ mix,   const float* __restrict__ times,
    const float* __restrict__ cp_table)
{
    int n = blockIdx.x, tid = threadIdx.x;
    __shared__ float sv[256];
    __shared__ int   si[256];
    __shared__ int   s_cidx, s_cnt;

    // argmax over 512 control planes (first index on ties)
    float best = -1e30f; int bi = 0;
    for(int j = tid; j < NCP; j += 256){
        float v = cpc[n*NCP + j];
        if(v > best){ best = v; bi = j; }
    }
    sv[tid] = best; si[tid] = bi; __syncthreads();
    for(int s = 128; s > 0; s >>= 1){
        if(tid < s){
            if(sv[tid+s] > sv[tid] || (sv[tid+s] == sv[tid] && si[tid+s] < si[tid])){
                sv[tid] = sv[tid+s]; si[tid] = si[tid+s];
            }
        }
        __syncthreads();
    }
    if(tid == 0){
        s_cidx = si[0];
        float b = -1e30f; int ii = 0;
        for(int j = 0; j < NFR; j++){ float v = times[n*NFR + j]; if(v > b){ b = v; ii = j; } }
        g_shift[n] = ii * (NSAMP / NFR);
        b = -1e30f; ii = 0;
        for(int j = 0; j < NVO; j++){ float v = voice[n*NVO + j]; if(v > b){ b = v; ii = j; } }
        g_vidx[n] = ii;
        b = -1e30f; ii = 0;
        for(int j = 0; j < NVB; j++){ float v = room[n*NVB + j]; if(v > b){ b = v; ii = j; } }
        g_ridx[n] = ii;
        float x0 = mix[n*2], x1 = mix[n*2 + 1];
        float mm = fmaxf(x0, x1);
        float e0 = expf(x0 - mm), e1 = expf(x1 - mm);
        g_m0[n] = e0 / (e0 + e1);
        g_m1[n] = e1 / (e0 + e1);
        g_amp[n] = fabsf(amp[n]);
    }
    __syncthreads();

    // top-K threshold over selected cp row (values in [0,1) -> bit-monotone)
    const float* row = cp_table + (size_t)s_cidx * (NFR*CPD);
    float rv[8];
    #pragma unroll
    for(int j = 0; j < 8; j++) rv[j] = row[tid + 256*j];
    unsigned lo = 0u, hi = 0x7F800000u;
    while(hi - lo > 1u){
        unsigned mid = lo + ((hi - lo) >> 1);
        int c = 0;
        #pragma unroll
        for(int j = 0; j < 8; j++) c += (__float_as_uint(rv[j]) >= mid) ? 1 : 0;
        si[tid] = c; __syncthreads();
        for(int s = 128; s > 0; s >>= 1){
            if(tid < s) si[tid] += si[tid+s];
            __syncthreads();
        }
        if(tid == 0) s_cnt = si[0];
        __syncthreads();
        if(s_cnt >= KSP) lo = mid; else hi = mid;
    }
    for(int idx = tid; idx < NFR*CPD; idx += 256){
        int f = idx >> 4, c = idx & 15;
        float v = row[c*NFR + f];
        float keep = (__float_as_uint(v) >= lo) ? v : 0.f;
        g_ctrl[n*NFR*CPD + idx] = fmaxf(keep, 0.f);
    }
}

// M[v] = W_ih[v] @ W_in[v] — parallel Kahan-fp32 split-K, one block per (v, i)
__global__ __launch_bounds__(128) void k_collapse(
    const float* __restrict__ w_ih, const float* __restrict__ w_in)
{
    int blk = blockIdx.x;           // 0..1023
    int v = blk >> 7, i = blk & 127;
    int t = threadIdx.x;            // 128
    const float* wr = w_ih + ((size_t)v*HID + i) * WINL;
    const float* wc = w_in + (size_t)v*WINL*CPD;
    float s[CPD], comp[CPD];
    #pragma unroll
    for(int c = 0; c < CPD; c++){ s[c] = 0.f; comp[c] = 0.f; }
    for(int k = t; k < WINL; k += 128){
        float a = wr[k];
        const float4* p = (const float4*)(wc + (size_t)k*CPD);
        float4 q[4] = {p[0], p[1], p[2], p[3]};
        const float* qs = (const float*)q;
        #pragma unroll
        for(int c = 0; c < CPD; c++){
            float y = fmaf(a, qs[c], -comp[c]);
            float tt = s[c] + y;
            comp[c] = (tt - s[c]) - y;
            s[c] = tt;
        }
    }
    __shared__ float red[128 * CPD];
    #pragma unroll
    for(int c = 0; c < CPD; c++) red[t*CPD + c] = s[c];
    __syncthreads();
    for(int st = 64; st > 0; st >>= 1){
        if(t < st){
            #pragma unroll
            for(int c = 0; c < CPD; c++) red[t*CPD + c] += red[(t+st)*CPD + c];
        }
        __syncthreads();
    }
    if(t < CPD) g_M[(v*HID + i)*CPD + t] = red[t];
}

// persistent RNN: one block per event
__global__ __launch_bounds__(256) void k_rnn(const float* __restrict__ w_hh){
    int n = blockIdx.x, t = threadIdx.x;
    int i = t & 127, half = t >> 7;
    int v = g_vidx[n];
    __shared__ float ctrl_s[NFR*CPD];
    __shared__ float h_s[HID];
    __shared__ float part_s[256];

    float W[64];
    const float* wh = w_hh + ((size_t)v*HID + i) * HID + half*64;
    #pragma unroll
    for(int k = 0; k < 64; k++) W[k] = wh[k];
    float M[CPD];
    const float* mp = g_M + (v*HID + i)*CPD;
    #pragma unroll
    for(int c = 0; c < CPD; c++) M[c] = mp[c];
    for(int idx = t; idx < NFR*CPD; idx += 256) ctrl_s[idx] = g_ctrl[n*NFR*CPD + idx];
    if(t < HID) h_s[t] = 0.f;
    __syncthreads();

    float* hsout = g_hs + (size_t)n*NFR*HID;
    for(int f = 0; f < NFR; f++){
        float p = 0.f;
        const float* hb = h_s + half*64;
        #pragma unroll
        for(int k = 0; k < 64; k++) p += W[k] * hb[k];
        part_s[t] = p;
        __syncthreads();
        if(half == 0){
            float inp = 0.f;
            #pragma unroll
            for(int c = 0; c < CPD; c++) inp += M[c] * ctrl_s[f*CPD + c];
            float h = tanhf(p + part_s[t + 128] + inp);
            h_s[i] = h;
            hsout[f*HID + i] = h;
        }
        __syncthreads();
    }
}

// sig[f,w] = sin( hs[f,:] . w_out[v,w,:] )
__global__ __launch_bounds__(256) void k_wout(const float* __restrict__ w_out){
    int wt = blockIdx.x, n = blockIdx.y, t = threadIdx.x;
    int v = g_vidx[n];
    const float* A  = g_hs + (size_t)n*NFR*HID;
    const float* Bm = w_out + (size_t)v*WINL*HID + (size_t)wt*128*HID;
    __shared__ float As[32*132];
    __shared__ float Bs[32*132];
    int tx = t & 15, ty = t >> 4;
    int f0 = ty*8, w0 = tx*8;
    float acc[8][8];
    #pragma unroll
    for(int i = 0; i < 8; i++)
        #pragma unroll
        for(int j = 0; j < 8; j++) acc[i][j] = 0.f;

    for(int ks = 0; ks < 4; ks++){
        int k0 = ks*32;
        #pragma unroll
        for(int r = 0; r < 4; r++){
            int idx4 = t + 256*r;
            int rr = idx4 >> 3, kk4 = idx4 & 7;
            float4 va = *(const float4*)(A  + (size_t)rr*HID + k0 + kk4*4);
            float4 vb = *(const float4*)(Bm + (size_t)rr*HID + k0 + kk4*4);
            As[(kk4*4+0)*132 + rr] = va.x; As[(kk4*4+1)*132 + rr] = va.y;
            As[(kk4*4+2)*132 + rr] = va.z; As[(kk4*4+3)*132 + rr] = va.w;
            Bs[(kk4*4+0)*132 + rr] = vb.x; Bs[(kk4*4+1)*132 + rr] = vb.y;
            Bs[(kk4*4+2)*132 + rr] = vb.z; Bs[(kk4*4+3)*132 + rr] = vb.w;
        }
        __syncthreads();
        #pragma unroll
        for(int k = 0; k < 32; k++){
            float4 a0 = *(const float4*)&As[k*132 + f0];
            float4 a1 = *(const float4*)&As[k*132 + f0 + 4];
            float4 b0 = *(const float4*)&Bs[k*132 + w0];
            float4 b1 = *(const float4*)&Bs[k*132 + w0 + 4];
            float a[8] = {a0.x,a0.y,a0.z,a0.w,a1.x,a1.y,a1.z,a1.w};
            float b[8] = {b0.x,b0.y,b0.z,b0.w,b1.x,b1.y,b1.z,b1.w};
            #pragma unroll
            for(int i = 0; i < 8; i++)
                #pragma unroll
                for(int j = 0; j < 8; j++) acc[i][j] += a[i]*b[j];
        }
        __syncthreads();
    }
    float* out = g_sig + (size_t)n*NSAMP + wt*128;
    #pragma unroll
    for(int i = 0; i < 8; i++)
        #pragma unroll
        for(int j = 0; j < 8; j++)
            out[(size_t)(f0+i)*WINL + w0 + j] = sinf(acc[i][j]);
}

// F1 column pass (forward) over real input, + inter-pass twiddle.
template<int SEL>
__global__ __launch_bounds__(512) void k_col_fwd(const float* __restrict__ rin_ext){
    __shared__ float2 s[8*LSTR];
    int n = blockIdx.y, col0 = blockIdx.x*8, tid = threadIdx.x;
    const float* src = (SEL == 0 ? rin_ext : g_sig) + (size_t)n*NSAMP;
    for(int idx = tid; idx < 4096; idx += 512){
        int r = idx >> 3, c = idx & 7;
        float val = (r < 256) ? src[(size_t)r*512 + col0 + c] : 0.f;
        s[c*LSTR + skew(r)] = make_float2(val, 0.f);
    }
    __syncthreads();
    dif512(&s[(tid >> 6)*LSTR], tid & 63);
    __syncthreads();
    float2* dst = (SEL == 0 ? g_vspec : g_spec) + (size_t)n*NFFT;
    for(int idx = tid; idx < 4096; idx += 512){
        int r = idx >> 3, c = idx & 7;
        int n2 = col0 + c;
        dst[(size_t)r*512 + n2] = cmul(s[c*LSTR + skew(r)], g_tw[rev9(r)*n2]);
    }
}

// Row pass. MODE 0: F2 on verb spectra. MODE 1: fused F2 + spectral-mul*(1/N) + I1 + conj twiddle.
template<int MODE>
__global__ __launch_bounds__(512) void k_row(){
    __shared__ float2 s[8*LSTR];
    int n = blockIdx.y, row0 = blockIdx.x*8, tid = threadIdx.x;
    float2* base = (MODE == 0 ? g_vspec : g_spec) + (size_t)n*NFFT + (size_t)row0*512;
    for(int idx = tid; idx < 4096; idx += 512){
        int r = idx >> 9, e = idx & 511;
        s[r*LSTR + skew(e)] = base[(size_t)r*512 + e];
    }
    __syncthreads();
    dif512(&s[(tid >> 6)*LSTR], tid & 63);
    __syncthreads();
    if(MODE == 0){
        for(int idx = tid; idx < 4096; idx += 512){
            int r = idx >> 9, e = idx & 511;
            base[(size_t)r*512 + e] = s[r*LSTR + skew(e)];
        }
    } else {
        const float2* vs = g_vspec + (size_t)g_ridx[n]*NFFT + (size_t)row0*512;
        const float sc = 1.f / (float)NFFT;
        for(int idx = tid; idx < 4096; idx += 512){
            int r = idx >> 9, e = idx & 511;
            float2 p = cmul(s[r*LSTR + skew(e)], vs[(size_t)r*512 + e]);
            s[r*LSTR + skew(e)] = make_float2(p.x*sc, p.y*sc);
        }
        __syncthreads();
        dit512(&s[(tid >> 6)*LSTR], tid & 63);
        __syncthreads();
        for(int idx = tid; idx < 4096; idx += 512){
            int r = idx >> 9, e = idx & 511;
            int k1 = rev9(row0 + r);
            base[(size_t)r*512 + e] = cmulc(s[r*LSTR + skew(e)], g_tw[k1*e]);
        }
    }
}

// I2 column pass (inverse) + epilogue: wet/dry mix, |amp|, shift as row-gather (zero-fill).
__global__ __launch_bounds__(512) void k_col_inv(float* __restrict__ out){
    __shared__ float2 s[8*LSTR];
    int n = blockIdx.y, col0 = blockIdx.x*8, tid = threadIdx.x;
    const float2* src = g_spec + (size_t)n*NFFT;
    for(int idx = tid; idx < 4096; idx += 512){
        int r = idx >> 3, c = idx & 7;
        s[c*LSTR + skew(r)] = src[(size_t)r*512 + col0 + c];
    }
    __syncthreads();
    dit512(&s[(tid >> 6)*LSTR], tid & 63);
    __syncthreads();
    float m0 = g_m0[n], m1 = g_m1[n], am = g_amp[n];
    int d512 = g_shift[n] >> 9;    // shift is a multiple of 1024 -> row-pure shift
    const float* dry = g_sig + (size_t)n*NSAMP;
    float* o = out + (size_t)n*NSAMP;
    for(int idx = tid; idx < 2048; idx += 512){
        int rp = idx >> 3, c = idx & 7;     // rp = output row (0..255)
        int col = col0 + c;
        int r = rp - d512;
        float vout = 0.f;
        if(r >= 0){
            int t = r*512 + col;
            float wet = s[c*LSTR + skew(r)].x;
            vout = (wet * m0 + dry[t] * m1) * am;
        }
        o[rp*512 + col] = vout;
    }
}

extern "C" void kernel_launch(void* const* d_in, const int* in_sizes, int n_in,
                              void* d_out, int out_size) {
    const float* voice = (const float*)d_in[0];
    const float* cpc   = (const float*)d_in[1];
    const float* amp   = (const float*)d_in[2];
    const float* room  = (const float*)d_in[3];
    const float* mix   = (const float*)d_in[4];
    const float* times = (const float*)d_in[5];
    const float* cp_table = (const float*)d_in[6];
    const float* verbs = (const float*)d_in[7];
    const float* w_in  = (const float*)d_in[8];
    const float* w_ih  = (const float*)d_in[9];
    const float* w_hh  = (const float*)d_in[10];
    const float* w_out = (const float*)d_in[11];
    float* out = (float*)d_out;

    k_twtab<<<2, 512>>>();
    k_twiddle<<<NFFT/512, 512>>>();
    k_prep<<<NEV, 256>>>(voice, cpc, amp, room, mix, times, cp_table);
    k_collapse<<<NVO*HID, 128>>>(w_ih, w_in);
    k_rnn<<<NEV, 256>>>(w_hh);
    k_wout<<<dim3(8, NEV), 256>>>(w_out);
    k_col_fwd<0><<<dim3(64, NVB), 512>>>(verbs);
    k_row<0><<<dim3(64, NVB), 512>>>();
    k_col_fwd<1><<<dim3(64, NEV), 512>>>(nullptr);
    k_row<1><<<dim3(64, NEV), 512>>>();
    k_col_inv<<<dim3(64, NEV), 512>>>(out);
}

// round 5
// speedup vs baseline: 2.6575x; 2.1732x over previous
#include <cuda_runtime.h>
#include <math.h>

#define NEV   128
#define NPAIR 64
#define NSAMP 131072
#define NFFT  262144
#define NFR   128
#define WINL  1024
#define CPD   16
#define NCP   512
#define NVO   8
#define NVB   16
#define HID   128
#define KSP   128
#define LSTR  576

__device__ float2 g_twtab[1024];                     // [0:512) W512^k ; [512:1024) W_N^k
__device__ float2 g_spec[(size_t)NPAIR * NFFT];      // 128 MB packed spectra
__device__ float2 g_vspec[(size_t)NVB * NFFT];       // 32 MB verb spectra
__device__ float  g_sig[(size_t)NEV * NSAMP];
__device__ float  g_hs[(size_t)NEV * NFR * HID];
__device__ float  g_ctrl[NEV * NFR * CPD];
__device__ float  g_M[NVO * HID * CPD];
__device__ int    g_vidx[NEV], g_ridx[NEV], g_shift[NEV];
__device__ float  g_m0[NEV], g_m1[NEV], g_amp[NEV];
__device__ int    g_pairA[257], g_pairB[257];

__device__ __forceinline__ int skew(int i){ return i + (i >> 3); }
__device__ __forceinline__ float2 cadd(float2 a, float2 b){ return make_float2(a.x+b.x, a.y+b.y); }
__device__ __forceinline__ float2 csub(float2 a, float2 b){ return make_float2(a.x-b.x, a.y-b.y); }
__device__ __forceinline__ float2 cmul(float2 a, float2 b){ return make_float2(a.x*b.x - a.y*b.y, a.x*b.y + a.y*b.x); }
__device__ __forceinline__ float2 cmulc(float2 a, float2 b){ return make_float2(a.x*b.x + a.y*b.y, a.y*b.x - a.x*b.y); }
__device__ __forceinline__ int rev9(int p){ return ((p & 7) << 6) | (p & 56) | (p >> 6); }

// W_N^{idx} from the 4KB factored table (idx < 2^18)
__device__ __forceinline__ float2 twN(int idx){
    int k = idx & (NFFT - 1);
    return cmul(g_twtab[k >> 9], g_twtab[512 + (k & 511)]);
}

template<bool INV>
__device__ __forceinline__ float2 mulmi(float2 a){
    return INV ? make_float2(-a.y, a.x) : make_float2(a.y, -a.x);
}

template<bool INV>
__device__ __forceinline__ void dft8(float2* v){
    float2 t0 = cadd(v[0], v[4]), t1 = csub(v[0], v[4]);
    float2 t2 = cadd(v[2], v[6]), t3 = mulmi<INV>(csub(v[2], v[6]));
    float2 t4 = cadd(v[1], v[5]), t5 = csub(v[1], v[5]);
    float2 t6 = cadd(v[3], v[7]), t7 = mulmi<INV>(csub(v[3], v[7]));
    float2 a0 = cadd(t0, t2), a2 = csub(t0, t2);
    float2 a1 = cadd(t1, t3), a3 = csub(t1, t3);
    float2 b0 = cadd(t4, t6), b2 = csub(t4, t6);
    float2 b1 = cadd(t5, t7), b3 = csub(t5, t7);
    const float r = 0.70710678118654752440f;
    float2 w1 = INV ? make_float2(r,  r) : make_float2(r, -r);
    float2 w3 = INV ? make_float2(-r, r) : make_float2(-r, -r);
    b1 = cmul(b1, w1); b2 = mulmi<INV>(b2); b3 = cmul(b3, w3);
    v[0] = cadd(a0, b0); v[4] = csub(a0, b0);
    v[1] = cadd(a1, b1); v[5] = csub(a1, b1);
    v[2] = cadd(a2, b2); v[6] = csub(a2, b2);
    v[3] = cadd(a3, b3); v[7] = csub(a3, b3);
}

// DIF 512 = radix-8^3, natural in -> octal-digit-reversed out.
__device__ __forceinline__ void dif512(float2* L, int t){
    float2 v[8];
    #pragma unroll
    for(int m = 0; m < 8; m++) v[m] = L[skew(t + 64*m)];
    dft8<false>(v);
    #pragma unroll
    for(int m = 1; m < 8; m++) v[m] = cmul(v[m], g_twtab[(t*m) & 511]);
    #pragma unroll
    for(int m = 0; m < 8; m++) L[skew(t + 64*m)] = v[m];
    __syncthreads();
    int base = (t >> 3) << 6, j = t & 7;
    #pragma unroll
    for(int m = 0; m < 8; m++) v[m] = L[skew(base + j + 8*m)];
    dft8<false>(v);
    #pragma unroll
    for(int m = 1; m < 8; m++) v[m] = cmul(v[m], g_twtab[((j*m) << 3) & 511]);
    #pragma unroll
    for(int m = 0; m < 8; m++) L[skew(base + j + 8*m)] = v[m];
    __syncthreads();
    base = t << 3;
    #pragma unroll
    for(int m = 0; m < 8; m++) v[m] = L[skew(base + m)];
    dft8<false>(v);
    #pragma unroll
    for(int m = 0; m < 8; m++) L[skew(base + m)] = v[m];
}

// DIT 512: digit-reversed in -> natural out, conjugate twiddles (unscaled inverse).
__device__ __forceinline__ void dit512(float2* L, int t){
    float2 v[8];
    int base = t << 3;
    #pragma unroll
    for(int m = 0; m < 8; m++) v[m] = L[skew(base + m)];
    dft8<true>(v);
    #pragma unroll
    for(int m = 0; m < 8; m++) L[skew(base + m)] = v[m];
    __syncthreads();
    base = (t >> 3) << 6; int j = t & 7;
    #pragma unroll
    for(int m = 0; m < 8; m++) v[m] = L[skew(base + j + 8*m)];
    #pragma unroll
    for(int m = 1; m < 8; m++) v[m] = cmulc(v[m], g_twtab[((j*m) << 3) & 511]);
    dft8<true>(v);
    #pragma unroll
    for(int m = 0; m < 8; m++) L[skew(base + j + 8*m)] = v[m];
    __syncthreads();
    #pragma unroll
    for(int m = 0; m < 8; m++) v[m] = L[skew(t + 64*m)];
    #pragma unroll
    for(int m = 1; m < 8; m++) v[m] = cmulc(v[m], g_twtab[(t*m) & 511]);
    dft8<true>(v);
    #pragma unroll
    for(int m = 0; m < 8; m++) L[skew(t + 64*m)] = v[m];
}

__global__ void k_twtab(){
    int k = blockIdx.x * blockDim.x + threadIdx.x;
    if(k < 1024){
        double a;
        if(k < 512) a = -6.283185307179586476925286766559 * (double)k / 512.0;
        else        a = -6.283185307179586476925286766559 * (double)(k - 512) / (double)NFFT;
        double s, c; sincos(a, &s, &c);
        g_twtab[k] = make_float2((float)c, (float)s);
    }
}

__global__ void k_pairlist(){
    if(threadIdx.x == 0 && blockIdx.x == 0){
        int cnt = 0;
        for(int p = 0; p < 512; p++){
            int k1 = rev9(p);
            int pp = rev9((512 - k1) & 511);
            if(p <= pp){ g_pairA[cnt] = p; g_pairB[cnt] = pp; cnt++; }
        }
    }
}

__global__ __launch_bounds__(256) void k_prep(
    const float* __restrict__ voice, const float* __restrict__ cpc,
    const float* __restrict__ amp,   const float* __restrict__ room,
    const float* __restrict__ mix,   const float* __restrict__ times,
    const float* __restrict__ cp_table)
{
    int n = blockIdx.x, tid = threadIdx.x;
    __shared__ float sv[256];
    __shared__ int   si[256];
    __shared__ int   s_cidx, s_cnt;

    float best = -1e30f; int bi = 0;
    for(int j = tid; j < NCP; j += 256){
        float v = cpc[n*NCP + j];
        if(v > best){ best = v; bi = j; }
    }
    sv[tid] = best; si[tid] = bi; __syncthreads();
    for(int s = 128; s > 0; s >>= 1){
        if(tid < s){
            if(sv[tid+s] > sv[tid] || (sv[tid+s] == sv[tid] && si[tid+s] < si[tid])){
                sv[tid] = sv[tid+s]; si[tid] = si[tid+s];
            }
        }
        __syncthreads();
    }
    if(tid == 0){
        s_cidx = si[0];
        float b = -1e30f; int ii = 0;
        for(int j = 0; j < NFR; j++){ float v = times[n*NFR + j]; if(v > b){ b = v; ii = j; } }
        g_shift[n] = ii * (NSAMP / NFR);
        b = -1e30f; ii = 0;
        for(int j = 0; j < NVO; j++){ float v = voice[n*NVO + j]; if(v > b){ b = v; ii = j; } }
        g_vidx[n] = ii;
        b = -1e30f; ii = 0;
        for(int j = 0; j < NVB; j++){ float v = room[n*NVB + j]; if(v > b){ b = v; ii = j; } }
        g_ridx[n] = ii;
        float x0 = mix[n*2], x1 = mix[n*2 + 1];
        float mm = fmaxf(x0, x1);
        float e0 = expf(x0 - mm), e1 = expf(x1 - mm);
        g_m0[n] = e0 / (e0 + e1);
        g_m1[n] = e1 / (e0 + e1);
        g_amp[n] = fabsf(amp[n]);
    }
    __syncthreads();

    const float* row = cp_table + (size_t)s_cidx * (NFR*CPD);
    float rv[8];
    #pragma unroll
    for(int j = 0; j < 8; j++) rv[j] = row[tid + 256*j];
    unsigned lo = 0u, hi = 0x7F800000u;
    while(hi - lo > 1u){
        unsigned mid = lo + ((hi - lo) >> 1);
        int c = 0;
        #pragma unroll
        for(int j = 0; j < 8; j++) c += (__float_as_uint(rv[j]) >= mid) ? 1 : 0;
        si[tid] = c; __syncthreads();
        for(int s = 128; s > 0; s >>= 1){
            if(tid < s) si[tid] += si[tid+s];
            __syncthreads();
        }
        if(tid == 0) s_cnt = si[0];
        __syncthreads();
        if(s_cnt >= KSP) lo = mid; else hi = mid;
    }
    for(int idx = tid; idx < NFR*CPD; idx += 256){
        int f = idx >> 4, c = idx & 15;
        float v = row[c*NFR + f];
        float keep = (__float_as_uint(v) >= lo) ? v : 0.f;
        g_ctrl[n*NFR*CPD + idx] = fmaxf(keep, 0.f);
    }
}

// M[v] = W_ih[v] @ W_in[v] — parallel Kahan-fp32 split-K
__global__ __launch_bounds__(128) void k_collapse(
    const float* __restrict__ w_ih, const float* __restrict__ w_in)
{
    int blk = blockIdx.x;
    int v = blk >> 7, i = blk & 127;
    int t = threadIdx.x;
    const float* wr = w_ih + ((size_t)v*HID + i) * WINL;
    const float* wc = w_in + (size_t)v*WINL*CPD;
    float s[CPD], comp[CPD];
    #pragma unroll
    for(int c = 0; c < CPD; c++){ s[c] = 0.f; comp[c] = 0.f; }
    for(int k = t; k < WINL; k += 128){
        float a = wr[k];
        const float4* p = (const float4*)(wc + (size_t)k*CPD);
        float4 q[4] = {p[0], p[1], p[2], p[3]};
        const float* qs = (const float*)q;
        #pragma unroll
        for(int c = 0; c < CPD; c++){
            float y = fmaf(a, qs[c], -comp[c]);
            float tt = s[c] + y;
            comp[c] = (tt - s[c]) - y;
            s[c] = tt;
        }
    }
    __shared__ float red[128 * CPD];
    #pragma unroll
    for(int c = 0; c < CPD; c++) red[t*CPD + c] = s[c];
    __syncthreads();
    for(int st = 64; st > 0; st >>= 1){
        if(t < st){
            #pragma unroll
            for(int c = 0; c < CPD; c++) red[t*CPD + c] += red[(t+st)*CPD + c];
        }
        __syncthreads();
    }
    if(t < CPD) g_M[(v*HID + i)*CPD + t] = red[t];
}

__global__ __launch_bounds__(256) void k_rnn(const float* __restrict__ w_hh){
    int n = blockIdx.x, t = threadIdx.x;
    int i = t & 127, half = t >> 7;
    int v = g_vidx[n];
    __shared__ float ctrl_s[NFR*CPD];
    __shared__ float h_s[HID];
    __shared__ float part_s[256];

    float W[64];
    const float* wh = w_hh + ((size_t)v*HID + i) * HID + half*64;
    #pragma unroll
    for(int k = 0; k < 64; k++) W[k] = wh[k];
    float M[CPD];
    const float* mp = g_M + (v*HID + i)*CPD;
    #pragma unroll
    for(int c = 0; c < CPD; c++) M[c] = mp[c];
    for(int idx = t; idx < NFR*CPD; idx += 256) ctrl_s[idx] = g_ctrl[n*NFR*CPD + idx];
    if(t < HID) h_s[t] = 0.f;
    __syncthreads();

    float* hsout = g_hs + (size_t)n*NFR*HID;
    for(int f = 0; f < NFR; f++){
        float p = 0.f;
        const float* hb = h_s + half*64;
        #pragma unroll
        for(int k = 0; k < 64; k++) p += W[k] * hb[k];
        part_s[t] = p;
        __syncthreads();
        if(half == 0){
            float inp = 0.f;
            #pragma unroll
            for(int c = 0; c < CPD; c++) inp += M[c] * ctrl_s[f*CPD + c];
            float h = tanhf(p + part_s[t + 128] + inp);
            h_s[i] = h;
            hsout[f*HID + i] = h;
        }
        __syncthreads();
    }
}

__global__ __launch_bounds__(256) void k_wout(const float* __restrict__ w_out){
    int wt = blockIdx.x, n = blockIdx.y, t = threadIdx.x;
    int v = g_vidx[n];
    const float* A  = g_hs + (size_t)n*NFR*HID;
    const float* Bm = w_out + (size_t)v*WINL*HID + (size_t)wt*128*HID;
    __shared__ float As[32*132];
    __shared__ float Bs[32*132];
    int tx = t & 15, ty = t >> 4;
    int f0 = ty*8, w0 = tx*8;
    float acc[8][8];
    #pragma unroll
    for(int i = 0; i < 8; i++)
        #pragma unroll
        for(int j = 0; j < 8; j++) acc[i][j] = 0.f;

    for(int ks = 0; ks < 4; ks++){
        int k0 = ks*32;
        #pragma unroll
        for(int r = 0; r < 4; r++){
            int idx4 = t + 256*r;
            int rr = idx4 >> 3, kk4 = idx4 & 7;
            float4 va = *(const float4*)(A  + (size_t)rr*HID + k0 + kk4*4);
            float4 vb = *(const float4*)(Bm + (size_t)rr*HID + k0 + kk4*4);
            As[(kk4*4+0)*132 + rr] = va.x; As[(kk4*4+1)*132 + rr] = va.y;
            As[(kk4*4+2)*132 + rr] = va.z; As[(kk4*4+3)*132 + rr] = va.w;
            Bs[(kk4*4+0)*132 + rr] = vb.x; Bs[(kk4*4+1)*132 + rr] = vb.y;
            Bs[(kk4*4+2)*132 + rr] = vb.z; Bs[(kk4*4+3)*132 + rr] = vb.w;
        }
        __syncthreads();
        #pragma unroll
        for(int k = 0; k < 32; k++){
            float4 a0 = *(const float4*)&As[k*132 + f0];
            float4 a1 = *(const float4*)&As[k*132 + f0 + 4];
            float4 b0 = *(const float4*)&Bs[k*132 + w0];
            float4 b1 = *(const float4*)&Bs[k*132 + w0 + 4];
            float a[8] = {a0.x,a0.y,a0.z,a0.w,a1.x,a1.y,a1.z,a1.w};
            float b[8] = {b0.x,b0.y,b0.z,b0.w,b1.x,b1.y,b1.z,b1.w};
            #pragma unroll
            for(int i = 0; i < 8; i++)
                #pragma unroll
                for(int j = 0; j < 8; j++) acc[i][j] += a[i]*b[j];
        }
        __syncthreads();
    }
    float* out = g_sig + (size_t)n*NSAMP + wt*128;
    #pragma unroll
    for(int i = 0; i < 8; i++)
        #pragma unroll
        for(int j = 0; j < 8; j++)
            out[(size_t)(f0+i)*WINL + w0 + j] = sinf(acc[i][j]);
}

// F1 column pass (forward). VERB=1: real verb -> g_vspec. VERB=0: packed pair of sigs -> g_spec.
template<int VERB>
__global__ __launch_bounds__(512) void k_col_fwd(const float* __restrict__ rin_ext){
    __shared__ float2 s[8*LSTR];
    int y = blockIdx.y, col0 = blockIdx.x*8, tid = threadIdx.x;
    const float* sa; const float* sb = nullptr; float2* dst;
    if(VERB){ sa = rin_ext + (size_t)y*NSAMP;        dst = g_vspec + (size_t)y*NFFT; }
    else    { sa = g_sig + (size_t)(2*y)*NSAMP; sb = g_sig + (size_t)(2*y+1)*NSAMP;
              dst = g_spec + (size_t)y*NFFT; }
    for(int idx = tid; idx < 4096; idx += 512){
        int r = idx >> 3, c = idx & 7;
        float re = 0.f, im = 0.f;
        if(r < 256){
            int o = r*512 + col0 + c;
            re = sa[o];
            if(!VERB) im = sb[o];
        }
        s[c*LSTR + skew(r)] = make_float2(re, im);
    }
    __syncthreads();
    dif512(&s[(tid >> 6)*LSTR], tid & 63);
    __syncthreads();
    for(int idx = tid; idx < 4096; idx += 512){
        int r = idx >> 3, c = idx & 7;
        int n2 = col0 + c;
        dst[(size_t)r*512 + n2] = cmul(s[c*LSTR + skew(r)], twN(rev9(r)*n2));
    }
}

// F2 row pass for verb spectra (store in scrambled (row,e) layout)
__global__ __launch_bounds__(512) void k_row_verb(){
    __shared__ float2 s[8*LSTR];
    int n = blockIdx.y, row0 = blockIdx.x*8, tid = threadIdx.x;
    float2* base = g_vspec + (size_t)n*NFFT + (size_t)row0*512;
    for(int idx = tid; idx < 4096; idx += 512){
        int r = idx >> 9, e = idx & 511;
        s[r*LSTR + skew(e)] = base[(size_t)r*512 + e];
    }
    __syncthreads();
    dif512(&s[(tid >> 6)*LSTR], tid & 63);
    __syncthreads();
    for(int idx = tid; idx < 4096; idx += 512){
        int r = idx >> 9, e = idx & 511;
        base[(size_t)r*512 + e] = s[r*LSTR + skew(e)];
    }
}

__device__ __forceinline__ int pzero(int e){   // partner col for the k1==0 row
    int k2 = rev9(e);
    return rev9((512 - k2) & 511);
}

// Fused: F2 + conj-unpack (2 events/complex FFT) + spectral mul (verb+dry fold, 1/N) + repack + I1 + conj twiddle
__global__ __launch_bounds__(128) void k_rowpair(){
    __shared__ float2 s[2*LSTR];
    int slot = blockIdx.x, p = blockIdx.y;
    int rows0 = g_pairA[slot], rows1 = g_pairB[slot];
    int line = threadIdx.x >> 6, t = threadIdx.x & 63;
    float2* base = g_spec + (size_t)p*NFFT;
    for(int idx = threadIdx.x; idx < 1024; idx += 128){
        int l = idx >> 9, e = idx & 511;
        int row = l ? rows1 : rows0;
        s[l*LSTR + skew(e)] = base[(size_t)row*512 + e];
    }
    __syncthreads();
    dif512(&s[line*LSTR], t);
    __syncthreads();

    int na = 2*p, nb = 2*p + 1;
    const float2* va = g_vspec + (size_t)g_ridx[na]*NFFT;
    const float2* vb = g_vspec + (size_t)g_ridx[nb]*NFFT;
    float m0a = g_m0[na], m1a = g_m1[na], m0b = g_m0[nb], m1b = g_m1[nb];
    const float invN = 1.f / (float)NFFT;

    float2 Z[8], Zp[8];
    #pragma unroll
    for(int q = 0; q < 8; q++){
        int idx = threadIdx.x + 128*q;
        int l = idx >> 9, e = idx & 511;
        int row = l ? rows1 : rows0;
        int k1 = rev9(row);
        int ep = (k1 == 0) ? pzero(e) : (511 - e);
        Z[q]  = s[l*LSTR + skew(e)];
        Zp[q] = s[(1 - l)*LSTR + skew(ep)];
    }
    __syncthreads();
    #pragma unroll
    for(int q = 0; q < 8; q++){
        int idx = threadIdx.x + 128*q;
        int l = idx >> 9, e = idx & 511;
        int row = l ? rows1 : rows0;
        // S1 = (Z + conj(Zp))/2 ; S2 = -i(Z - conj(Zp))/2
        float2 S1 = make_float2(0.5f*(Z[q].x + Zp[q].x), 0.5f*(Z[q].y - Zp[q].y));
        float2 S2 = make_float2(0.5f*(Z[q].y + Zp[q].y), -0.5f*(Z[q].x - Zp[q].x));
        float2 V1 = va[(size_t)row*512 + e];
        float2 V2 = vb[(size_t)row*512 + e];
        float2 M1 = make_float2(m0a*V1.x + m1a, m0a*V1.y);   // m0*V + m1 (dry folded)
        float2 M2 = make_float2(m0b*V2.x + m1b, m0b*V2.y);
        float2 W1 = cmul(S1, M1), W2 = cmul(S2, M2);
        s[l*LSTR + skew(e)] = make_float2((W1.x - W2.y)*invN, (W1.y + W2.x)*invN);
    }
    __syncthreads();
    dit512(&s[line*LSTR], t);
    __syncthreads();
    for(int idx = threadIdx.x; idx < 1024; idx += 128){
        int l = idx >> 9, e = idx & 511;
        int row = l ? rows1 : rows0;
        int k1 = rev9(row);
        base[(size_t)row*512 + e] = cmulc(s[l*LSTR + skew(e)], twN(k1*e));
    }
}

// I2 column pass (inverse, packed) + epilogue: |amp| + dirac row-shift, re->event 2p, im->event 2p+1
__global__ __launch_bounds__(512) void k_col_inv(float* __restrict__ out){
    __shared__ float2 s[8*LSTR];
    int p = blockIdx.y, col0 = blockIdx.x*8, tid = threadIdx.x;
    const float2* src = g_spec + (size_t)p*NFFT;
    for(int idx = tid; idx < 4096; idx += 512){
        int r = idx >> 3, c = idx & 7;
        s[c*LSTR + skew(r)] = src[(size_t)r*512 + col0 + c];
    }
    __syncthreads();
    dit512(&s[(tid >> 6)*LSTR], tid & 63);
    __syncthreads();
    int na = 2*p, nb = 2*p + 1;
    float aA = g_amp[na], aB = g_amp[nb];
    int dA = g_shift[na] >> 9, dB = g_shift[nb] >> 9;
    float* oA = out + (size_t)na*NSAMP;
    float* oB = out + (size_t)nb*NSAMP;
    for(int idx = tid; idx < 2048; idx += 512){
        int rp = idx >> 3, c = idx & 7;
        int col = col0 + c;
        int ra = rp - dA;
        oA[rp*512 + col] = (ra >= 0) ? s[c*LSTR + skew(ra)].x * aA : 0.f;
        int rb = rp - dB;
        oB[rp*512 + col] = (rb >= 0) ? s[c*LSTR + skew(rb)].y * aB : 0.f;
    }
}

extern "C" void kernel_launch(void* const* d_in, const int* in_sizes, int n_in,
                              void* d_out, int out_size) {
    const float* voice = (const float*)d_in[0];
    const float* cpc   = (const float*)d_in[1];
    const float* amp   = (const float*)d_in[2];
    const float* room  = (const float*)d_in[3];
    const float* mix   = (const float*)d_in[4];
    const float* times = (const float*)d_in[5];
    const float* cp_table = (const float*)d_in[6];
    const float* verbs = (const float*)d_in[7];
    const float* w_in  = (const float*)d_in[8];
    const float* w_ih  = (const float*)d_in[9];
    const float* w_hh  = (const float*)d_in[10];
    const float* w_out = (const float*)d_in[11];
    float* out = (float*)d_out;

    k_twtab<<<2, 512>>>();
    k_pairlist<<<1, 1>>>();
    k_prep<<<NEV, 256>>>(voice, cpc, amp, room, mix, times, cp_table);
    k_collapse<<<NVO*HID, 128>>>(w_ih, w_in);
    k_rnn<<<NEV, 256>>>(w_hh);
    k_wout<<<dim3(8, NEV), 256>>>(w_out);
    k_col_fwd<1><<<dim3(64, NVB), 512>>>(verbs);
    k_row_verb<<<dim3(64, NVB), 512>>>();
    k_col_fwd<0><<<dim3(64, NPAIR), 512>>>(nullptr);
    k_rowpair<<<dim3(257, NPAIR), 128>>>();
    k_col_inv<<<dim3(64, NPAIR), 512>>>(out);
}